// round 1
// baseline (speedup 1.0000x reference)
#include <cuda_runtime.h>
#include <math.h>

// ---------------- constants ----------------
#define Hd   1024
#define BATCH 8
#define SEQ  2048
#define MTOK (BATCH*SEQ)        // 16384
#define NENT 1000
#define TOPK 5
#define LNEPS 1e-5f
#define NEG_INF -3.4e38f

// output layout (floats), concatenated in reference return order
#define EF_OFF  0                         // entity_features  [8,2048,1024]
#define RF_OFF  (EF_OFF + MTOK*Hd)        // relation_features [8,1024]
#define RET_OFF (RF_OFF + BATCH*Hd)       // retrieved_entities [8,5,1024]
#define SIM_OFF (RET_OFF + BATCH*TOPK*Hd) // entity_similarities [8,1000]
#define IDX_OFF (SIM_OFF + BATCH*NENT)    // top_indices [8,5] (as float)
#define RO_OFF  (IDX_OFF + BATCH*TOPK)    // reasoning_output [8,1024]
#define VS_OFF  (RO_OFF + BATCH*Hd)       // validation_scores [8,1]

// ---------------- scratch (static device memory; no allocations) ----------------
__device__ float g_mid1[MTOK * 2*Hd];       // 128 MB
__device__ float g_pool_part[16 * BATCH*Hd];
__device__ float g_pooled[BATCH*Hd];
__device__ float g_part[8 * 8 * 2048];
__device__ float g_rmid[BATCH*Hd];
__device__ float g_rraw[BATCH*Hd];
__device__ float g_rin[BATCH*3*Hd];
__device__ float g_rmid2[BATCH*2*Hd];
__device__ float g_vmid[BATCH*512];
__device__ int   g_topidx[BATCH*TOPK];

// ---------------- helpers ----------------
__device__ __forceinline__ float gelu_erf(float x) {
    return 0.5f * x * (1.0f + erff(x * 0.70710678118654752f));
}
__device__ __forceinline__ float sigmoidf_(float x) {
    return 1.0f / (1.0f + expf(-x));
}
__device__ __forceinline__ float apply_act(float v, int act) {
    if (act == 1) return gelu_erf(v);
    if (act == 2) return sigmoidf_(v);
    return v;
}

// ---------------- big tiled SGEMM: C = act(A[MxK] @ W[KxN] + bias) ----------------
#define BM 128
#define BN 128
#define BK 16
__global__ __launch_bounds__(256) void gemm_bias_act(
    const float* __restrict__ A, const float* __restrict__ W,
    const float* __restrict__ bias, float* __restrict__ C,
    int M, int N, int K, int act)
{
    __shared__ float As[BK][BM];
    __shared__ float Bs[BK][BN];

    const int bn = blockIdx.x * BN;
    const int bm = blockIdx.y * BM;
    const int tid = threadIdx.x;
    const int tx = tid & 15;
    const int ty = tid >> 4;

    float acc[8][8];
#pragma unroll
    for (int i = 0; i < 8; i++)
#pragma unroll
        for (int j = 0; j < 8; j++) acc[i][j] = 0.0f;

    for (int k0 = 0; k0 < K; k0 += BK) {
#pragma unroll
        for (int l = 0; l < 2; l++) {
            int i = tid + 256 * l;          // 512 float4 slots for A tile
            int row = i >> 2;
            int c4 = (i & 3) * 4;
            float4 v = *(const float4*)&A[(size_t)(bm + row) * K + k0 + c4];
            As[c4 + 0][row] = v.x;
            As[c4 + 1][row] = v.y;
            As[c4 + 2][row] = v.z;
            As[c4 + 3][row] = v.w;
        }
#pragma unroll
        for (int l = 0; l < 2; l++) {
            int i = tid + 256 * l;          // 512 float4 slots for B tile
            int row = i >> 5;
            int c4 = (i & 31) * 4;
            float4 v = *(const float4*)&W[(size_t)(k0 + row) * N + bn + c4];
            *(float4*)&Bs[row][c4] = v;
        }
        __syncthreads();

#pragma unroll
        for (int k = 0; k < BK; k++) {
            float a[8], b[8];
#pragma unroll
            for (int i = 0; i < 8; i++) a[i] = As[k][ty * 8 + i];
#pragma unroll
            for (int j = 0; j < 8; j++) b[j] = Bs[k][tx * 8 + j];
#pragma unroll
            for (int i = 0; i < 8; i++)
#pragma unroll
                for (int j = 0; j < 8; j++) acc[i][j] = fmaf(a[i], b[j], acc[i][j]);
        }
        __syncthreads();
    }

#pragma unroll
    for (int i = 0; i < 8; i++) {
        int row = bm + ty * 8 + i;
#pragma unroll
        for (int j = 0; j < 8; j++) {
            int col = bn + tx * 8 + j;
            float v = acc[i][j] + bias[col];
            v = apply_act(v, act);
            C[(size_t)row * N + col] = v;
        }
    }
}

// ---------------- per-row LayerNorm over H=1024 (in-place safe) ----------------
__global__ __launch_bounds__(256) void ln_rows(
    const float* __restrict__ X, const float* __restrict__ g,
    const float* __restrict__ beta, float* __restrict__ Y)
{
    const int row = blockIdx.x;
    const int tid = threadIdx.x;
    const float* x = X + (size_t)row * Hd;
    float v[4];
    float s = 0.0f, q = 0.0f;
#pragma unroll
    for (int i = 0; i < 4; i++) {
        v[i] = x[tid + i * 256];
        s += v[i];
        q += v[i] * v[i];
    }
    __shared__ float sh1[256], sh2[256];
    sh1[tid] = s; sh2[tid] = q;
    __syncthreads();
    for (int o = 128; o; o >>= 1) {
        if (tid < o) { sh1[tid] += sh1[tid + o]; sh2[tid] += sh2[tid + o]; }
        __syncthreads();
    }
    float mu = sh1[0] * (1.0f / Hd);
    float var = sh2[0] * (1.0f / Hd) - mu * mu;
    float inv = rsqrtf(var + LNEPS);
    float* y = Y + (size_t)row * Hd;
#pragma unroll
    for (int i = 0; i < 4; i++) {
        int c = tid + i * 256;
        y[c] = (v[i] - mu) * inv * g[c] + beta[c];
    }
}

// ---------------- mean pool over sequence ----------------
__global__ void pool_partial(const float* __restrict__ hid)
{
    int idx = blockIdx.x * 256 + threadIdx.x;   // 0..8191
    int ss = blockIdx.y;                        // 0..15
    int b = idx >> 10, h = idx & 1023;
    float s = 0.0f;
    int s0 = ss * (SEQ / 16);
    const float* base = hid + ((size_t)b * SEQ + s0) * Hd + h;
#pragma unroll 4
    for (int t = 0; t < SEQ / 16; t++) s += base[(size_t)t * Hd];
    g_pool_part[ss * (BATCH * Hd) + idx] = s;
}
__global__ void pool_combine()
{
    int idx = blockIdx.x * 256 + threadIdx.x;
    float s = 0.0f;
#pragma unroll
    for (int ss = 0; ss < 16; ss++) s += g_pool_part[ss * (BATCH * Hd) + idx];
    g_pooled[idx] = s * (1.0f / SEQ);
}

// ---------------- small GEMM (8 rows) with deterministic K-split ----------------
#define KSPLIT 8
__global__ void sg_partial(const float* __restrict__ X, const float* __restrict__ W,
                           int K, int N)
{
    int n = blockIdx.x * blockDim.x + threadIdx.x;
    int ks = blockIdx.y;
    if (n >= N) return;
    int kchunk = K / KSPLIT;
    int k0 = ks * kchunk, k1 = k0 + kchunk;
    float acc[8];
#pragma unroll
    for (int r = 0; r < 8; r++) acc[r] = 0.0f;
    for (int k = k0; k < k1; k++) {
        float w = W[(size_t)k * N + n];
#pragma unroll
        for (int r = 0; r < 8; r++) acc[r] = fmaf(__ldg(&X[r * K + k]), w, acc[r]);
    }
#pragma unroll
    for (int r = 0; r < 8; r++) g_part[(ks * 8 + r) * N + n] = acc[r];
}
__global__ void sg_combine(const float* __restrict__ bias, float* __restrict__ Y,
                           int N, int act)
{
    int i = blockIdx.x * blockDim.x + threadIdx.x;
    if (i >= 8 * N) return;
    int r = i / N, n = i - r * N;
    float s = bias[n];
#pragma unroll
    for (int ks = 0; ks < KSPLIT; ks++) s += g_part[(ks * 8 + r) * N + n];
    Y[i] = apply_act(s, act);
}

// ---------------- entity similarities ----------------
__global__ __launch_bounds__(128) void sims_kernel(
    const float* __restrict__ E, const float* __restrict__ relf,
    float* __restrict__ sims)
{
    int n = blockIdx.x;
    int tid = threadIdx.x;
    __shared__ float rs[BATCH * Hd];
    for (int i = tid; i < BATCH * Hd; i += 128) rs[i] = relf[i];
    __syncthreads();
    float acc[8];
#pragma unroll
    for (int r = 0; r < 8; r++) acc[r] = 0.0f;
    for (int k = tid; k < Hd; k += 128) {
        float e = E[(size_t)n * Hd + k];
#pragma unroll
        for (int r = 0; r < 8; r++) acc[r] = fmaf(e, rs[r * Hd + k], acc[r]);
    }
    __shared__ float red[8][128];
#pragma unroll
    for (int r = 0; r < 8; r++) red[r][tid] = acc[r];
    __syncthreads();
    for (int o = 64; o; o >>= 1) {
        if (tid < o) {
#pragma unroll
            for (int r = 0; r < 8; r++) red[r][tid] += red[r][tid + o];
        }
        __syncthreads();
    }
    if (tid < 8) sims[tid * NENT + n] = red[tid][0];
}

// ---------------- top-5 (desc, lowest index on ties) ----------------
__global__ __launch_bounds__(256) void topk_kernel(const float* __restrict__ sims,
                                                   float* __restrict__ fidx_out)
{
    int b = blockIdx.x;
    int tid = threadIdx.x;
    __shared__ float sv[1024];
    for (int i = tid; i < 1024; i += 256)
        sv[i] = (i < NENT) ? sims[b * NENT + i] : NEG_INF;
    __syncthreads();
    __shared__ float bv[256];
    __shared__ int bi[256];
    for (int t = 0; t < TOPK; t++) {
        float best = NEG_INF; int besti = 0;
        for (int i = tid; i < NENT; i += 256) {
            float vv = sv[i];
            if (vv > best) { best = vv; besti = i; }
        }
        bv[tid] = best; bi[tid] = besti;
        __syncthreads();
        for (int o = 128; o; o >>= 1) {
            if (tid < o) {
                if (bv[tid + o] > bv[tid] ||
                    (bv[tid + o] == bv[tid] && bi[tid + o] < bi[tid])) {
                    bv[tid] = bv[tid + o]; bi[tid] = bi[tid + o];
                }
            }
            __syncthreads();
        }
        if (tid == 0) {
            g_topidx[b * TOPK + t] = bi[0];
            fidx_out[b * TOPK + t] = (float)bi[0];
            sv[bi[0]] = NEG_INF;
        }
        __syncthreads();
    }
}

// ---------------- gather retrieved entities + build reasoning input ----------------
__global__ __launch_bounds__(256) void build_rin(
    const float* __restrict__ E, const float* __restrict__ relf,
    float* __restrict__ ret_out)
{
    int b = blockIdx.x;
    for (int h = threadIdx.x; h < Hd; h += 256) {
        float s = 0.0f;
#pragma unroll
        for (int k = 0; k < TOPK; k++) {
            float v = E[(size_t)g_topidx[b * TOPK + k] * Hd + h];
            ret_out[((size_t)b * TOPK + k) * Hd + h] = v;
            s += v;
        }
        g_rin[b * 3 * Hd + h]          = s * (1.0f / TOPK);
        g_rin[b * 3 * Hd + Hd + h]     = relf[b * Hd + h];
        g_rin[b * 3 * Hd + 2 * Hd + h] = g_pooled[b * Hd + h];
    }
}

// ---------------- launch ----------------
extern "C" void kernel_launch(void* const* d_in, const int* in_sizes, int n_in,
                              void* d_out, int out_size)
{
    const float* hid    = (const float*)d_in[0];
    const float* ent    = (const float*)d_in[1];
    const float* ee_w1  = (const float*)d_in[2];
    const float* ee_b1  = (const float*)d_in[3];
    const float* ee_w2  = (const float*)d_in[4];
    const float* ee_b2  = (const float*)d_in[5];
    const float* ee_g   = (const float*)d_in[6];
    const float* ee_be  = (const float*)d_in[7];
    const float* re_w1  = (const float*)d_in[8];
    const float* re_b1  = (const float*)d_in[9];
    const float* re_w2  = (const float*)d_in[10];
    const float* re_b2  = (const float*)d_in[11];
    const float* re_g   = (const float*)d_in[12];
    const float* re_be  = (const float*)d_in[13];
    const float* rn_w1  = (const float*)d_in[14];
    const float* rn_b1  = (const float*)d_in[15];
    const float* rn_w2  = (const float*)d_in[16];
    const float* rn_b2  = (const float*)d_in[17];
    const float* rn_g   = (const float*)d_in[18];
    const float* rn_be  = (const float*)d_in[19];
    const float* vn_w1  = (const float*)d_in[20];
    const float* vn_b1  = (const float*)d_in[21];
    const float* vn_w2  = (const float*)d_in[22];
    const float* vn_b2  = (const float*)d_in[23];
    float* out = (float*)d_out;

    float *mid1, *pooled, *rmid, *rraw, *rin, *rmid2, *vmid;
    cudaGetSymbolAddress((void**)&mid1,   g_mid1);
    cudaGetSymbolAddress((void**)&pooled, g_pooled);
    cudaGetSymbolAddress((void**)&rmid,   g_rmid);
    cudaGetSymbolAddress((void**)&rraw,   g_rraw);
    cudaGetSymbolAddress((void**)&rin,    g_rin);
    cudaGetSymbolAddress((void**)&rmid2,  g_rmid2);
    cudaGetSymbolAddress((void**)&vmid,   g_vmid);

    // 1) mean pool over sequence -> g_pooled
    pool_partial<<<dim3(32, 16), 256>>>(hid);
    pool_combine<<<32, 256>>>();

    // 2) entity encoder (dominant cost)
    gemm_bias_act<<<dim3(2 * Hd / BN, MTOK / BM), 256>>>(hid, ee_w1, ee_b1, mid1,
                                                         MTOK, 2 * Hd, Hd, 1);
    gemm_bias_act<<<dim3(Hd / BN, MTOK / BM), 256>>>(mid1, ee_w2, ee_b2, out + EF_OFF,
                                                     MTOK, Hd, 2 * Hd, 0);
    ln_rows<<<MTOK, 256>>>(out + EF_OFF, ee_g, ee_be, out + EF_OFF);

    // 3) relation encoder on pooled -> relation_features
    sg_partial<<<dim3(Hd / 256, KSPLIT), 256>>>(pooled, re_w1, Hd, Hd);
    sg_combine<<<(8 * Hd + 255) / 256, 256>>>(re_b1, rmid, Hd, 1);
    sg_partial<<<dim3(Hd / 256, KSPLIT), 256>>>(rmid, re_w2, Hd, Hd);
    sg_combine<<<(8 * Hd + 255) / 256, 256>>>(re_b2, rraw, Hd, 0);
    ln_rows<<<BATCH, 256>>>(rraw, re_g, re_be, out + RF_OFF);

    // 4) similarities, top-k, gather
    sims_kernel<<<NENT, 128>>>(ent, out + RF_OFF, out + SIM_OFF);
    topk_kernel<<<BATCH, 256>>>(out + SIM_OFF, out + IDX_OFF);
    build_rin<<<BATCH, 256>>>(ent, out + RF_OFF, out + RET_OFF);

    // 5) reasoning network
    sg_partial<<<dim3(2 * Hd / 256, KSPLIT), 256>>>(rin, rn_w1, 3 * Hd, 2 * Hd);
    sg_combine<<<(8 * 2 * Hd + 255) / 256, 256>>>(rn_b1, rmid2, 2 * Hd, 1);
    sg_partial<<<dim3(Hd / 256, KSPLIT), 256>>>(rmid2, rn_w2, 2 * Hd, Hd);
    sg_combine<<<(8 * Hd + 255) / 256, 256>>>(rn_b2, rraw, Hd, 0);
    ln_rows<<<BATCH, 256>>>(rraw, rn_g, rn_be, out + RO_OFF);

    // 6) validation network
    sg_partial<<<dim3(512 / 256, KSPLIT), 256>>>(out + RO_OFF, vn_w1, Hd, 512);
    sg_combine<<<(8 * 512 + 255) / 256, 256>>>(vn_b1, vmid, 512, 1);
    sg_partial<<<dim3(1, KSPLIT), 256>>>(vmid, vn_w2, 512, 1);
    sg_combine<<<1, 256>>>(vn_b2, out + VS_OFF, 1, 2);
}

// round 3
// speedup vs baseline: 2.0689x; 2.0689x over previous
#include <cuda_runtime.h>
#include <cuda_bf16.h>
#include <mma.h>
#include <math.h>
#include <stdint.h>

using namespace nvcuda;

// ---------------- constants ----------------
#define Hd   1024
#define BATCH 8
#define SEQ  2048
#define MTOK (BATCH*SEQ)        // 16384
#define NENT 1000
#define TOPK 5
#define LNEPS 1e-5f
#define NEG_INF -3.4e38f

// output layout (floats), concatenated in reference return order
#define EF_OFF  0                         // entity_features  [8,2048,1024]
#define RF_OFF  (EF_OFF + MTOK*Hd)        // relation_features [8,1024]
#define RET_OFF (RF_OFF + BATCH*Hd)       // retrieved_entities [8,5,1024]
#define SIM_OFF (RET_OFF + BATCH*TOPK*Hd) // entity_similarities [8,1000]
#define IDX_OFF (SIM_OFF + BATCH*NENT)    // top_indices [8,5] (as float)
#define RO_OFF  (IDX_OFF + BATCH*TOPK)    // reasoning_output [8,1024]
#define VS_OFF  (RO_OFF + BATCH*Hd)       // validation_scores [8,1]

// ---------------- scratch (static device memory; no allocations) ----------------
__device__ __align__(128) __nv_bfloat16 g_ahi[(size_t)MTOK * Hd];
__device__ __align__(128) __nv_bfloat16 g_alo[(size_t)MTOK * Hd];
__device__ __align__(128) __nv_bfloat16 g_mhi[(size_t)MTOK * 2*Hd];
__device__ __align__(128) __nv_bfloat16 g_mlo[(size_t)MTOK * 2*Hd];
__device__ __align__(128) __nv_bfloat16 g_wt1h[2*Hd * Hd];   // ee_w1^T hi [2048][1024]
__device__ __align__(128) __nv_bfloat16 g_wt1l[2*Hd * Hd];
__device__ __align__(128) __nv_bfloat16 g_wt2h[Hd * 2*Hd];   // ee_w2^T hi [1024][2048]
__device__ __align__(128) __nv_bfloat16 g_wt2l[Hd * 2*Hd];

__device__ float g_pool_part[16 * BATCH*Hd];
__device__ float g_pooled[BATCH*Hd];
__device__ float g_part[8 * 8 * 2048];
__device__ float g_rmid[BATCH*Hd];
__device__ float g_rraw[BATCH*Hd];
__device__ float g_rin[BATCH*3*Hd];
__device__ float g_rmid2[BATCH*2*Hd];
__device__ float g_vmid[BATCH*512];
__device__ int   g_topidx[BATCH*TOPK];

// ---------------- math helpers ----------------
__device__ __forceinline__ float gelu_erf(float x) {
    return 0.5f * x * (1.0f + erff(x * 0.70710678118654752f));
}
__device__ __forceinline__ float sigmoidf_(float x) {
    return 1.0f / (1.0f + expf(-x));
}
__device__ __forceinline__ float apply_act(float v, int act) {
    if (act == 1) return gelu_erf(v);
    if (act == 2) return sigmoidf_(v);
    return v;
}
__device__ __forceinline__ void split_bf16(float x, __nv_bfloat16& h, __nv_bfloat16& l) {
    h = __float2bfloat16_rn(x);
    l = __float2bfloat16_rn(x - __bfloat162float(h));
}

// ---------------- conversions ----------------
__global__ __launch_bounds__(256) void split_convert(
    const float* __restrict__ x, __nv_bfloat16* __restrict__ hi,
    __nv_bfloat16* __restrict__ lo, int n4)
{
    int i = blockIdx.x * 256 + threadIdx.x;
    if (i >= n4) return;
    float4 v = ((const float4*)x)[i];
    __nv_bfloat16 h0,l0,h1,l1,h2,l2,h3,l3;
    split_bf16(v.x,h0,l0); split_bf16(v.y,h1,l1);
    split_bf16(v.z,h2,l2); split_bf16(v.w,h3,l3);
    __nv_bfloat162* H = (__nv_bfloat162*)(hi + 4*(size_t)i);
    __nv_bfloat162* L = (__nv_bfloat162*)(lo + 4*(size_t)i);
    H[0] = __nv_bfloat162(h0,h1); H[1] = __nv_bfloat162(h2,h3);
    L[0] = __nv_bfloat162(l0,l1); L[1] = __nv_bfloat162(l2,l3);
}

// W[K][N] fp32 -> WT_hi/lo [N][K] bf16
__global__ __launch_bounds__(256) void transpose_split(
    const float* __restrict__ W, __nv_bfloat16* __restrict__ th,
    __nv_bfloat16* __restrict__ tl, int K, int N)
{
    __shared__ float t[32][33];
    int n0 = blockIdx.x * 32, k0 = blockIdx.y * 32;
    int tx = threadIdx.x & 31, ty = threadIdx.x >> 5;   // 32x8
#pragma unroll
    for (int r = 0; r < 32; r += 8)
        t[ty + r][tx] = W[(size_t)(k0 + ty + r) * N + n0 + tx];
    __syncthreads();
#pragma unroll
    for (int r = 0; r < 32; r += 8) {
        float v = t[tx][ty + r];
        __nv_bfloat16 h, l; split_bf16(v, h, l);
        size_t o = (size_t)(n0 + ty + r) * K + k0 + tx;
        th[o] = h; tl[o] = l;
    }
}

// ---------------- WMMA split-bf16 GEMM ----------------
// C[M][N] = act(A @ B^T + bias), A = ahi+alo [M][K], B rows = bhi+blo [N][K].
// mode 0: write fp32 C.  mode 1: gelu, split into (chi, clo) bf16.
#define BKC 32
#define LDAB 40                              // bf16 leading dim with pad
#define TILEB (128 * LDAB * 2)               // 10240 B per operand tile
#define STAGEB (4 * TILEB)                   // Ah, Al, Bh, Bl
#define GSMEM (2 * STAGEB)                   // 81920 B

__device__ __forceinline__ void cpa16(void* s, const void* g) {
    uint32_t sa;
    asm("{ .reg .u64 tmp; cvta.to.shared.u64 tmp, %1; cvt.u32.u64 %0, tmp; }"
        : "=r"(sa) : "l"(s));
    asm volatile("cp.async.cg.shared.global [%0], [%1], 16;" :: "r"(sa), "l"(g) : "memory");
}

__device__ __forceinline__ void load_tile_async(
    const __nv_bfloat16* __restrict__ g, int row0, int K, int kc,
    char* s, int tid)
{
    int r = tid >> 2, c = tid & 3;     // 64 rows x 4 chunks of 16B
#pragma unroll
    for (int h = 0; h < 2; h++) {
        int row = r + h * 64;
        const __nv_bfloat16* gp = g + (size_t)(row0 + row) * K + kc + c * 8;
        cpa16(s + row * (LDAB * 2) + c * 16, gp);
    }
}

__global__ __launch_bounds__(256) void gemm_tc(
    const __nv_bfloat16* __restrict__ ahi, const __nv_bfloat16* __restrict__ alo,
    const __nv_bfloat16* __restrict__ bhi, const __nv_bfloat16* __restrict__ blo,
    const float* __restrict__ bias,
    float* __restrict__ Cf, __nv_bfloat16* __restrict__ chi, __nv_bfloat16* __restrict__ clo,
    int M, int N, int K, int mode)
{
    extern __shared__ char sm_[];
    const int tid = threadIdx.x;
    const int wid = tid >> 5;
    const int wm = wid & 3;          // 4 warps along M (32 rows each)
    const int wn = wid >> 2;         // 2 warps along N (64 cols each)
    const int bn = blockIdx.x * 128;
    const int bm = blockIdx.y * 128;

    wmma::fragment<wmma::accumulator, 16, 16, 16, float> acc[2][4];
#pragma unroll
    for (int mi = 0; mi < 2; mi++)
#pragma unroll
        for (int ni = 0; ni < 4; ni++) wmma::fill_fragment(acc[mi][ni], 0.0f);

    const int NCH = K / BKC;

    // prologue: prefetch chunk 0 into stage 0
    {
        char* st = sm_;
        load_tile_async(ahi, bm, K, 0, st + 0*TILEB, tid);
        load_tile_async(alo, bm, K, 0, st + 1*TILEB, tid);
        load_tile_async(bhi, bn, K, 0, st + 2*TILEB, tid);
        load_tile_async(blo, bn, K, 0, st + 3*TILEB, tid);
        asm volatile("cp.async.commit_group;" ::: "memory");
    }

    for (int ch = 0; ch < NCH; ch++) {
        if (ch + 1 < NCH) {
            char* st = sm_ + ((ch + 1) & 1) * STAGEB;
            int kc = (ch + 1) * BKC;
            load_tile_async(ahi, bm, K, kc, st + 0*TILEB, tid);
            load_tile_async(alo, bm, K, kc, st + 1*TILEB, tid);
            load_tile_async(bhi, bn, K, kc, st + 2*TILEB, tid);
            load_tile_async(blo, bn, K, kc, st + 3*TILEB, tid);
            asm volatile("cp.async.commit_group;" ::: "memory");
            asm volatile("cp.async.wait_group 1;" ::: "memory");
        } else {
            asm volatile("cp.async.wait_group 0;" ::: "memory");
        }
        __syncthreads();

        char* st = sm_ + (ch & 1) * STAGEB;
        const __nv_bfloat16* Ah = (const __nv_bfloat16*)(st + 0*TILEB);
        const __nv_bfloat16* Al = (const __nv_bfloat16*)(st + 1*TILEB);
        const __nv_bfloat16* Bh = (const __nv_bfloat16*)(st + 2*TILEB);
        const __nv_bfloat16* Bl = (const __nv_bfloat16*)(st + 3*TILEB);

#pragma unroll
        for (int kk = 0; kk < BKC; kk += 16) {
            wmma::fragment<wmma::matrix_a, 16, 16, 16, __nv_bfloat16, wmma::row_major> ah[2], al[2];
            wmma::fragment<wmma::matrix_b, 16, 16, 16, __nv_bfloat16, wmma::col_major> bh[4], bl[4];
#pragma unroll
            for (int mi = 0; mi < 2; mi++) {
                int r0 = wm * 32 + mi * 16;
                wmma::load_matrix_sync(ah[mi], Ah + r0 * LDAB + kk, LDAB);
                wmma::load_matrix_sync(al[mi], Al + r0 * LDAB + kk, LDAB);
            }
#pragma unroll
            for (int ni = 0; ni < 4; ni++) {
                int n0 = wn * 64 + ni * 16;
                wmma::load_matrix_sync(bh[ni], Bh + n0 * LDAB + kk, LDAB);
                wmma::load_matrix_sync(bl[ni], Bl + n0 * LDAB + kk, LDAB);
            }
#pragma unroll
            for (int mi = 0; mi < 2; mi++)
#pragma unroll
                for (int ni = 0; ni < 4; ni++) {
                    wmma::mma_sync(acc[mi][ni], ah[mi], bh[ni], acc[mi][ni]);
                    wmma::mma_sync(acc[mi][ni], ah[mi], bl[ni], acc[mi][ni]);
                    wmma::mma_sync(acc[mi][ni], al[mi], bh[ni], acc[mi][ni]);
                }
        }
        __syncthreads();
    }

    // ---- epilogue via SMEM staging ----
    float* Cs = (float*)sm_;                 // 128 x 132 fp32 = 67584 B
#pragma unroll
    for (int mi = 0; mi < 2; mi++)
#pragma unroll
        for (int ni = 0; ni < 4; ni++)
            wmma::store_matrix_sync(Cs + (wm * 32 + mi * 16) * 132 + wn * 64 + ni * 16,
                                    acc[mi][ni], 132, wmma::mem_row_major);
    __syncthreads();

    for (int i = tid; i < 128 * 128; i += 256) {
        int row = i >> 7, col = i & 127;
        float v = Cs[row * 132 + col] + bias[bn + col];
        size_t o = (size_t)(bm + row) * N + bn + col;
        if (mode == 0) {
            Cf[o] = v;
        } else {
            float gv = gelu_erf(v);
            __nv_bfloat16 h, l; split_bf16(gv, h, l);
            chi[o] = h; clo[o] = l;
        }
    }
}

// ---------------- per-row LayerNorm over H=1024 (in-place safe) ----------------
__global__ __launch_bounds__(256) void ln_rows(
    const float* __restrict__ X, const float* __restrict__ g,
    const float* __restrict__ beta, float* __restrict__ Y)
{
    const int row = blockIdx.x;
    const int tid = threadIdx.x;
    const float* x = X + (size_t)row * Hd;
    float v[4];
    float s = 0.0f, q = 0.0f;
#pragma unroll
    for (int i = 0; i < 4; i++) {
        v[i] = x[tid + i * 256];
        s += v[i];
        q += v[i] * v[i];
    }
    __shared__ float sh1[256], sh2[256];
    sh1[tid] = s; sh2[tid] = q;
    __syncthreads();
    for (int o = 128; o; o >>= 1) {
        if (tid < o) { sh1[tid] += sh1[tid + o]; sh2[tid] += sh2[tid + o]; }
        __syncthreads();
    }
    float mu = sh1[0] * (1.0f / Hd);
    float var = sh2[0] * (1.0f / Hd) - mu * mu;
    float inv = rsqrtf(var + LNEPS);
    float* y = Y + (size_t)row * Hd;
#pragma unroll
    for (int i = 0; i < 4; i++) {
        int c = tid + i * 256;
        y[c] = (v[i] - mu) * inv * g[c] + beta[c];
    }
}

// ---------------- mean pool over sequence ----------------
__global__ void pool_partial(const float* __restrict__ hid)
{
    int idx = blockIdx.x * 256 + threadIdx.x;
    int ss = blockIdx.y;
    int b = idx >> 10, h = idx & 1023;
    float s = 0.0f;
    int s0 = ss * (SEQ / 16);
    const float* base = hid + ((size_t)b * SEQ + s0) * Hd + h;
#pragma unroll 4
    for (int t = 0; t < SEQ / 16; t++) s += base[(size_t)t * Hd];
    g_pool_part[ss * (BATCH * Hd) + idx] = s;
}
__global__ void pool_combine()
{
    int idx = blockIdx.x * 256 + threadIdx.x;
    float s = 0.0f;
#pragma unroll
    for (int ss = 0; ss < 16; ss++) s += g_pool_part[ss * (BATCH * Hd) + idx];
    g_pooled[idx] = s * (1.0f / SEQ);
}

// ---------------- small GEMM (8 rows) with deterministic K-split ----------------
#define KSPLIT 8
__global__ void sg_partial(const float* __restrict__ X, const float* __restrict__ W,
                           int K, int N)
{
    int n = blockIdx.x * blockDim.x + threadIdx.x;
    int ks = blockIdx.y;
    if (n >= N) return;
    int kchunk = K / KSPLIT;
    int k0 = ks * kchunk, k1 = k0 + kchunk;
    float acc[8];
#pragma unroll
    for (int r = 0; r < 8; r++) acc[r] = 0.0f;
    for (int k = k0; k < k1; k++) {
        float w = W[(size_t)k * N + n];
#pragma unroll
        for (int r = 0; r < 8; r++) acc[r] = fmaf(__ldg(&X[r * K + k]), w, acc[r]);
    }
#pragma unroll
    for (int r = 0; r < 8; r++) g_part[(ks * 8 + r) * N + n] = acc[r];
}
__global__ void sg_combine(const float* __restrict__ bias, float* __restrict__ Y,
                           int N, int act)
{
    int i = blockIdx.x * blockDim.x + threadIdx.x;
    if (i >= 8 * N) return;
    int r = i / N, n = i - r * N;
    float s = bias[n];
#pragma unroll
    for (int ks = 0; ks < KSPLIT; ks++) s += g_part[(ks * 8 + r) * N + n];
    Y[i] = apply_act(s, act);
}

// ---------------- entity similarities ----------------
__global__ __launch_bounds__(128) void sims_kernel(
    const float* __restrict__ E, const float* __restrict__ relf,
    float* __restrict__ sims)
{
    int n = blockIdx.x;
    int tid = threadIdx.x;
    __shared__ float rs[BATCH * Hd];
    for (int i = tid; i < BATCH * Hd; i += 128) rs[i] = relf[i];
    __syncthreads();
    float acc[8];
#pragma unroll
    for (int r = 0; r < 8; r++) acc[r] = 0.0f;
    for (int k = tid; k < Hd; k += 128) {
        float e = E[(size_t)n * Hd + k];
#pragma unroll
        for (int r = 0; r < 8; r++) acc[r] = fmaf(e, rs[r * Hd + k], acc[r]);
    }
    __shared__ float red[8][128];
#pragma unroll
    for (int r = 0; r < 8; r++) red[r][tid] = acc[r];
    __syncthreads();
    for (int o = 64; o; o >>= 1) {
        if (tid < o) {
#pragma unroll
            for (int r = 0; r < 8; r++) red[r][tid] += red[r][tid + o];
        }
        __syncthreads();
    }
    if (tid < 8) sims[tid * NENT + n] = red[tid][0];
}

// ---------------- top-5 (desc, lowest index on ties) ----------------
__global__ __launch_bounds__(256) void topk_kernel(const float* __restrict__ sims,
                                                   float* __restrict__ fidx_out)
{
    int b = blockIdx.x;
    int tid = threadIdx.x;
    __shared__ float sv[1024];
    for (int i = tid; i < 1024; i += 256)
        sv[i] = (i < NENT) ? sims[b * NENT + i] : NEG_INF;
    __syncthreads();
    __shared__ float bv[256];
    __shared__ int bi[256];
    for (int t = 0; t < TOPK; t++) {
        float best = NEG_INF; int besti = 0;
        for (int i = tid; i < NENT; i += 256) {
            float vv = sv[i];
            if (vv > best) { best = vv; besti = i; }
        }
        bv[tid] = best; bi[tid] = besti;
        __syncthreads();
        for (int o = 128; o; o >>= 1) {
            if (tid < o) {
                if (bv[tid + o] > bv[tid] ||
                    (bv[tid + o] == bv[tid] && bi[tid + o] < bi[tid])) {
                    bv[tid] = bv[tid + o]; bi[tid] = bi[tid + o];
                }
            }
            __syncthreads();
        }
        if (tid == 0) {
            g_topidx[b * TOPK + t] = bi[0];
            fidx_out[b * TOPK + t] = (float)bi[0];
            sv[bi[0]] = NEG_INF;
        }
        __syncthreads();
    }
}

// ---------------- gather retrieved entities + build reasoning input ----------------
__global__ __launch_bounds__(256) void build_rin(
    const float* __restrict__ E, const float* __restrict__ relf,
    float* __restrict__ ret_out)
{
    int b = blockIdx.x;
    for (int h = threadIdx.x; h < Hd; h += 256) {
        float s = 0.0f;
#pragma unroll
        for (int k = 0; k < TOPK; k++) {
            float v = E[(size_t)g_topidx[b * TOPK + k] * Hd + h];
            ret_out[((size_t)b * TOPK + k) * Hd + h] = v;
            s += v;
        }
        g_rin[b * 3 * Hd + h]          = s * (1.0f / TOPK);
        g_rin[b * 3 * Hd + Hd + h]     = relf[b * Hd + h];
        g_rin[b * 3 * Hd + 2 * Hd + h] = g_pooled[b * Hd + h];
    }
}

// ---------------- launch ----------------
extern "C" void kernel_launch(void* const* d_in, const int* in_sizes, int n_in,
                              void* d_out, int out_size)
{
    const float* hid    = (const float*)d_in[0];
    const float* ent    = (const float*)d_in[1];
    const float* ee_w1  = (const float*)d_in[2];
    const float* ee_b1  = (const float*)d_in[3];
    const float* ee_w2  = (const float*)d_in[4];
    const float* ee_b2  = (const float*)d_in[5];
    const float* ee_g   = (const float*)d_in[6];
    const float* ee_be  = (const float*)d_in[7];
    const float* re_w1  = (const float*)d_in[8];
    const float* re_b1  = (const float*)d_in[9];
    const float* re_w2  = (const float*)d_in[10];
    const float* re_b2  = (const float*)d_in[11];
    const float* re_g   = (const float*)d_in[12];
    const float* re_be  = (const float*)d_in[13];
    const float* rn_w1  = (const float*)d_in[14];
    const float* rn_b1  = (const float*)d_in[15];
    const float* rn_w2  = (const float*)d_in[16];
    const float* rn_b2  = (const float*)d_in[17];
    const float* rn_g   = (const float*)d_in[18];
    const float* rn_be  = (const float*)d_in[19];
    const float* vn_w1  = (const float*)d_in[20];
    const float* vn_b1  = (const float*)d_in[21];
    const float* vn_w2  = (const float*)d_in[22];
    const float* vn_b2  = (const float*)d_in[23];
    float* out = (float*)d_out;

    __nv_bfloat16 *ahi, *alo, *mhi, *mlo, *wt1h, *wt1l, *wt2h, *wt2l;
    float *pooled, *rmid, *rraw, *rin, *rmid2, *vmid;
    cudaGetSymbolAddress((void**)&ahi,  g_ahi);
    cudaGetSymbolAddress((void**)&alo,  g_alo);
    cudaGetSymbolAddress((void**)&mhi,  g_mhi);
    cudaGetSymbolAddress((void**)&mlo,  g_mlo);
    cudaGetSymbolAddress((void**)&wt1h, g_wt1h);
    cudaGetSymbolAddress((void**)&wt1l, g_wt1l);
    cudaGetSymbolAddress((void**)&wt2h, g_wt2h);
    cudaGetSymbolAddress((void**)&wt2l, g_wt2l);
    cudaGetSymbolAddress((void**)&pooled, g_pooled);
    cudaGetSymbolAddress((void**)&rmid,   g_rmid);
    cudaGetSymbolAddress((void**)&rraw,   g_rraw);
    cudaGetSymbolAddress((void**)&rin,    g_rin);
    cudaGetSymbolAddress((void**)&rmid2,  g_rmid2);
    cudaGetSymbolAddress((void**)&vmid,   g_vmid);

    cudaFuncSetAttribute(gemm_tc, cudaFuncAttributeMaxDynamicSharedMemorySize, GSMEM);

    // 0) conversions
    split_convert<<<(MTOK * Hd / 4 + 255) / 256, 256>>>(hid, ahi, alo, MTOK * Hd / 4);
    transpose_split<<<dim3(2 * Hd / 32, Hd / 32), 256>>>(ee_w1, wt1h, wt1l, Hd, 2 * Hd);
    transpose_split<<<dim3(Hd / 32, 2 * Hd / 32), 256>>>(ee_w2, wt2h, wt2l, 2 * Hd, Hd);

    // 1) mean pool over sequence -> g_pooled
    pool_partial<<<dim3(32, 16), 256>>>(hid);
    pool_combine<<<32, 256>>>();

    // 2) entity encoder on tensor cores (split-bf16 WMMA, fp32 accumulate)
    gemm_tc<<<dim3(2 * Hd / 128, MTOK / 128), 256, GSMEM>>>(
        ahi, alo, wt1h, wt1l, ee_b1, nullptr, mhi, mlo, MTOK, 2 * Hd, Hd, 1);
    gemm_tc<<<dim3(Hd / 128, MTOK / 128), 256, GSMEM>>>(
        mhi, mlo, wt2h, wt2l, ee_b2, out + EF_OFF, nullptr, nullptr, MTOK, Hd, 2 * Hd, 0);
    ln_rows<<<MTOK, 256>>>(out + EF_OFF, ee_g, ee_be, out + EF_OFF);

    // 3) relation encoder on pooled -> relation_features
    sg_partial<<<dim3(Hd / 256, KSPLIT), 256>>>(pooled, re_w1, Hd, Hd);
    sg_combine<<<(8 * Hd + 255) / 256, 256>>>(re_b1, rmid, Hd, 1);
    sg_partial<<<dim3(Hd / 256, KSPLIT), 256>>>(rmid, re_w2, Hd, Hd);
    sg_combine<<<(8 * Hd + 255) / 256, 256>>>(re_b2, rraw, Hd, 0);
    ln_rows<<<BATCH, 256>>>(rraw, re_g, re_be, out + RF_OFF);

    // 4) similarities, top-k, gather
    sims_kernel<<<NENT, 128>>>(ent, out + RF_OFF, out + SIM_OFF);
    topk_kernel<<<BATCH, 256>>>(out + SIM_OFF, out + IDX_OFF);
    build_rin<<<BATCH, 256>>>(ent, out + RF_OFF, out + RET_OFF);

    // 5) reasoning network
    sg_partial<<<dim3(2 * Hd / 256, KSPLIT), 256>>>(rin, rn_w1, 3 * Hd, 2 * Hd);
    sg_combine<<<(8 * 2 * Hd + 255) / 256, 256>>>(rn_b1, rmid2, 2 * Hd, 1);
    sg_partial<<<dim3(Hd / 256, KSPLIT), 256>>>(rmid2, rn_w2, 2 * Hd, Hd);
    sg_combine<<<(8 * Hd + 255) / 256, 256>>>(rn_b2, rraw, Hd, 0);
    ln_rows<<<BATCH, 256>>>(rraw, rn_g, rn_be, out + RO_OFF);

    // 6) validation network
    sg_partial<<<dim3(512 / 256, KSPLIT), 256>>>(out + RO_OFF, vn_w1, Hd, 512);
    sg_combine<<<(8 * 512 + 255) / 256, 256>>>(vn_b1, vmid, 512, 1);
    sg_partial<<<dim3(1, KSPLIT), 256>>>(vmid, vn_w2, 512, 1);
    sg_combine<<<1, 256>>>(vn_b2, out + VS_OFF, 1, 2);
}